// round 1
// baseline (speedup 1.0000x reference)
#include <cuda_runtime.h>
#include <math.h>

// Problem dims (fixed by the dataset):
//   x         : [2, 2048, 4096]  -> M = 4096, H(K1) = 4096
//   w_gate_up : [22016, 4096]    -> N1 = 22016 (= 2*I)
//   w_down    : [4096, 11008]    -> N2 = 4096, K2 = I = 11008
//   out       : [2, 2048, 4096]  fp32
//
// Pipeline: gu = x @ w_gate_up^T ; h = silu(gu[:, :I]) * gu[:, I:] ; out = h @ w_down^T

#define BM 128
#define BN 128
#define BK 8
#define TM 8
#define TN 8

static const int M_DIM = 4096;
static const int H_DIM = 4096;
static const int I_DIM = 11008;

// Scratch (allocation-free rule: __device__ globals)
__device__ float g_gu[(size_t)4096 * 22016];   // ~361 MB
__device__ float g_h[(size_t)4096 * 11008];    // ~180 MB

// C[M,N] = A[M,K] (row-major) * B[N,K]^T (B row-major)
// All of M,N divisible by 128 and K divisible by 8 — no bounds checks.
__global__ __launch_bounds__(256)
void sgemm_tn(const float* __restrict__ A,
              const float* __restrict__ B,
              float* __restrict__ C,
              int M, int N, int K)
{
    __shared__ __align__(16) float As[BK][BM];
    __shared__ __align__(16) float Bs[BK][BN];

    const int bm  = blockIdx.y * BM;
    const int bn  = blockIdx.x * BN;
    const int tid = threadIdx.x;          // 0..255

    // Tile loads: 128 rows x 8 cols = 1024 floats = 256 threads x float4
    const int ldrow = tid >> 1;            // 0..127
    const int ldcol = (tid & 1) << 2;      // 0 or 4

    const int tx = tid & 15;               // 0..15 -> N micro-tile
    const int ty = tid >> 4;               // 0..15 -> M micro-tile

    const float* Ag = A + (size_t)(bm + ldrow) * K + ldcol;
    const float* Bg = B + (size_t)(bn + ldrow) * K + ldcol;

    float acc[TM][TN];
    #pragma unroll
    for (int i = 0; i < TM; i++)
        #pragma unroll
        for (int j = 0; j < TN; j++)
            acc[i][j] = 0.0f;

    for (int k0 = 0; k0 < K; k0 += BK) {
        float4 av = *reinterpret_cast<const float4*>(Ag + k0);
        float4 bv = *reinterpret_cast<const float4*>(Bg + k0);
        As[ldcol + 0][ldrow] = av.x;
        As[ldcol + 1][ldrow] = av.y;
        As[ldcol + 2][ldrow] = av.z;
        As[ldcol + 3][ldrow] = av.w;
        Bs[ldcol + 0][ldrow] = bv.x;
        Bs[ldcol + 1][ldrow] = bv.y;
        Bs[ldcol + 2][ldrow] = bv.z;
        Bs[ldcol + 3][ldrow] = bv.w;
        __syncthreads();

        #pragma unroll
        for (int k = 0; k < BK; k++) {
            float ra[TM], rb[TN];
            #pragma unroll
            for (int i = 0; i < TM; i += 4) {
                float4 v = *reinterpret_cast<const float4*>(&As[k][ty * TM + i]);
                ra[i + 0] = v.x; ra[i + 1] = v.y; ra[i + 2] = v.z; ra[i + 3] = v.w;
            }
            #pragma unroll
            for (int j = 0; j < TN; j += 4) {
                float4 v = *reinterpret_cast<const float4*>(&Bs[k][tx * TN + j]);
                rb[j + 0] = v.x; rb[j + 1] = v.y; rb[j + 2] = v.z; rb[j + 3] = v.w;
            }
            #pragma unroll
            for (int i = 0; i < TM; i++)
                #pragma unroll
                for (int j = 0; j < TN; j++)
                    acc[i][j] = fmaf(ra[i], rb[j], acc[i][j]);
        }
        __syncthreads();
    }

    #pragma unroll
    for (int i = 0; i < TM; i++) {
        float* Crow = C + (size_t)(bm + ty * TM + i) * N + bn + tx * TN;
        #pragma unroll
        for (int j = 0; j < TN; j += 4) {
            float4 v = make_float4(acc[i][j], acc[i][j + 1], acc[i][j + 2], acc[i][j + 3]);
            *reinterpret_cast<float4*>(Crow + j) = v;
        }
    }
}

// h[m, i] = silu(gu[m, i]) * gu[m, I + i]     (vectorized by 4; 11008 % 4 == 0)
__global__ void swiglu_kernel(const float* __restrict__ gu,
                              float* __restrict__ h,
                              int m_dim, int i_dim)
{
    const int i4_per_row = i_dim >> 2;                 // 2752
    long idx = (long)blockIdx.x * blockDim.x + threadIdx.x;
    long total4 = (long)m_dim * i4_per_row;
    if (idx >= total4) return;

    int m  = (int)(idx / i4_per_row);
    int i4 = (int)(idx % i4_per_row);

    const float4 g4 = *reinterpret_cast<const float4*>(gu + (size_t)m * (2 * i_dim) + i4 * 4);
    const float4 u4 = *reinterpret_cast<const float4*>(gu + (size_t)m * (2 * i_dim) + i_dim + i4 * 4);

    float4 r;
    r.x = (g4.x / (1.0f + expf(-g4.x))) * u4.x;
    r.y = (g4.y / (1.0f + expf(-g4.y))) * u4.y;
    r.z = (g4.z / (1.0f + expf(-g4.z))) * u4.z;
    r.w = (g4.w / (1.0f + expf(-g4.w))) * u4.w;
    *reinterpret_cast<float4*>(h + (size_t)m * i_dim + i4 * 4) = r;
}

extern "C" void kernel_launch(void* const* d_in, const int* in_sizes, int n_in,
                              void* d_out, int out_size)
{
    const float* x         = (const float*)d_in[0];
    const float* w_gate_up = (const float*)d_in[1];
    const float* w_down    = (const float*)d_in[2];
    float* out             = (float*)d_out;

    float *gu_ptr = nullptr, *h_ptr = nullptr;
    cudaGetSymbolAddress((void**)&gu_ptr, g_gu);
    cudaGetSymbolAddress((void**)&h_ptr, g_h);

    dim3 block(256);

    // GEMM1: gu[M, 2I] = x[M, H] * w_gate_up[2I, H]^T
    dim3 grid1((2 * I_DIM) / BN, M_DIM / BM);   // (172, 32)
    sgemm_tn<<<grid1, block>>>(x, w_gate_up, gu_ptr, M_DIM, 2 * I_DIM, H_DIM);

    // SwiGLU: h[M, I]
    long total4 = (long)M_DIM * (I_DIM / 4);
    swiglu_kernel<<<(unsigned)((total4 + 255) / 256), 256>>>(gu_ptr, h_ptr, M_DIM, I_DIM);

    // GEMM2: out[M, H] = h[M, I] * w_down[H, I]^T
    dim3 grid2(H_DIM / BN, M_DIM / BM);         // (32, 32)
    sgemm_tn<<<grid2, block>>>(h_ptr, w_down, out, M_DIM, H_DIM, I_DIM);
}

// round 3
// speedup vs baseline: 7.2385x; 7.2385x over previous
#include <cuda_runtime.h>
#include <cuda_bf16.h>
#include <cstdint>
#include <math.h>

typedef __nv_bfloat16 bf16;

// ---- arch gate: tcgen05 only exists on arch-specific (sm_103a) targets ----
#if defined(__CUDA_ARCH__) && ( \
      defined(__CUDA_ARCH_FEAT_SM103_ALL) || \
      defined(__CUDA_ARCH_FEAT_SM100_ALL) || \
      (defined(__CUDA_ARCH_SPECIFIC__) && (__CUDA_ARCH_SPECIFIC__ == 1030 || __CUDA_ARCH_SPECIFIC__ == 1000)) )
#define HAS_TC 1
#else
#define HAS_TC 0
#endif

// ---- problem dims ----
#define M_DIM 4096
#define H_DIM 4096
#define I_DIM 11008

// ---- GEMM tile config (tcgen05 path) ----
#define BM 128
#define BN 256
#define KC 64           // bf16 elems per K-chunk -> 128B rows (SW128 atom width)
#define NTHREADS 256

// ---- smem stage layout (bytes) ----
#define OFF_AHI 0
#define OFF_ALO (16*1024)
#define OFF_BHI (32*1024)
#define OFF_BLO (64*1024)
#define STAGE_BYTES (96*1024)
#define SMEM_STAGE0 1024
#define SMEM_TOTAL (SMEM_STAGE0 + 2*STAGE_BYTES)   // 197632 B

// idesc: kind::f16, dtype=F32(1<<4), atype=BF16(1<<7), btype=BF16(1<<10),
// N=256 -> (256/8)<<17, M=128 -> (128/16)<<24
#define MMA_IDESC ((1u<<4)|(1u<<7)|(1u<<10)|((BN/8)<<17)|((BM/16)<<24))

// SW128 K-major smem descriptor base (layout=2, version=1, SBO=64, LBO=1)
#define SMEM_DESC_BASE_SW128 \
    ((uint64_t(2) << 61) | (uint64_t(1) << 46) | (uint64_t(64) << 32) | (uint64_t(1) << 16))

// ---- device scratch (allocation-free rule) ----
__device__ bf16 g_x_hi [(size_t)M_DIM * H_DIM];
__device__ bf16 g_x_lo [(size_t)M_DIM * H_DIM];
__device__ bf16 g_wgu_hi[(size_t)2 * I_DIM * H_DIM];
__device__ bf16 g_wgu_lo[(size_t)2 * I_DIM * H_DIM];
__device__ bf16 g_wd_hi [(size_t)H_DIM * I_DIM];
__device__ bf16 g_wd_lo [(size_t)H_DIM * I_DIM];
__device__ bf16 g_h_hi  [(size_t)M_DIM * I_DIM];
__device__ bf16 g_h_lo  [(size_t)M_DIM * I_DIM];

// ======================= generic PTX helpers =======================

__device__ __forceinline__ uint32_t smem_u32(const void* p) {
    uint32_t a;
    asm("{ .reg .u64 t; cvta.to.shared.u64 t, %1; cvt.u32.u64 %0, t; }" : "=r"(a) : "l"(p));
    return a;
}

__device__ __forceinline__ uint32_t elect_one() {
    uint32_t pred;
    asm volatile("{\n\t.reg .pred p;\n\telect.sync _|p, 0xFFFFFFFF;\n\tselp.b32 %0, 1, 0, p;\n\t}" : "=r"(pred));
    return pred;
}

__device__ __forceinline__ uint32_t swz(uint32_t off) { return off ^ ((off >> 3) & 0x70); }

__device__ __forceinline__ void cp16(uint32_t dst, const void* src) {
    asm volatile("cp.async.cg.shared.global [%0], [%1], 16;" :: "r"(dst), "l"(src) : "memory");
}
__device__ __forceinline__ void cp_commit() {
    asm volatile("cp.async.commit_group;" ::: "memory");
}

__device__ __forceinline__ uint64_t make_desc(uint32_t addr) {
    return SMEM_DESC_BASE_SW128 | ((uint64_t)(addr >> 4) & 0x3FFF);
}

#define MBARRIER_INIT(mbar, count) \
    asm volatile("mbarrier.init.shared.b64 [%0], %1;" \
        :: "r"((uint32_t)(mbar)), "r"((uint32_t)(count)) : "memory")

#define MBARRIER_WAIT_PARITY(mbar_addr, phase_parity) do { \
    uint32_t _mbar = (uint32_t)(mbar_addr); \
    uint32_t _parity = (uint32_t)(phase_parity); \
    uint32_t _done; \
    asm volatile( \
        "{\n\t.reg .pred p;\n\t" \
        "mbarrier.try_wait.parity.acquire.cta.shared::cta.b64 p, [%1], %2;\n\t" \
        "selp.b32 %0, 1, 0, p;\n\t}" \
        : "=r"(_done) : "r"(_mbar), "r"(_parity) : "memory"); \
    if (!_done) { \
        asm volatile( \
            "{\n\t.reg .pred P1;\n\t" \
            "WAIT_LOOP_%=:\n\t" \
            "mbarrier.try_wait.parity.acquire.cta.shared::cta.b64 P1, [%0], %1, 0x989680;\n\t" \
            "@P1 bra.uni WAIT_DONE_%=;\n\t" \
            "bra.uni WAIT_LOOP_%=;\n\t" \
            "WAIT_DONE_%=:\n\t}" \
            :: "r"(_mbar), "r"(_parity) : "memory"); \
    } \
} while (0)

// ======================= tcgen05 helpers (only referenced when HAS_TC) =======================

__device__ __forceinline__ void mma_ss(uint32_t d, uint64_t ad, uint64_t bd,
                                       uint32_t idesc, uint32_t en) {
    asm volatile(
        "{\n\t"
        ".reg .pred p;\n\t"
        "setp.ne.u32 p, %4, 0;\n\t"
        "tcgen05.mma.cta_group::1.kind::f16 [%0], %1, %2, %3, {%5, %5, %5, %5}, p;\n\t"
        "}"
        :: "r"(d), "l"(ad), "l"(bd), "r"(idesc), "r"(en), "r"(0u)
        : "memory");
}

__device__ __forceinline__ void tc_alloc(uint32_t smem_result_addr, uint32_t nCols) {
    asm volatile("tcgen05.alloc.cta_group::1.sync.aligned.shared::cta.b32 [%0], %1;"
        :: "r"(smem_result_addr), "r"(nCols) : "memory");
}
__device__ __forceinline__ void tc_dealloc(uint32_t tmem_addr, uint32_t nCols) {
    asm volatile("tcgen05.dealloc.cta_group::1.sync.aligned.b32 %0, %1;"
        :: "r"(tmem_addr), "r"(nCols));
}
__device__ __forceinline__ void tc_relinquish() {
    asm volatile("tcgen05.relinquish_alloc_permit.cta_group::1.sync.aligned;");
}
__device__ __forceinline__ void tc_commit(uint32_t mbar) {
    asm volatile("tcgen05.commit.cta_group::1.mbarrier::arrive::one.shared::cluster.b64 [%0];"
        :: "r"(mbar) : "memory");
}
__device__ __forceinline__ void tc_fence_after() {
    asm volatile("tcgen05.fence::after_thread_sync;" ::: "memory");
}
__device__ __forceinline__ void tc_wait_ld() {
    asm volatile("tcgen05.wait::ld.sync.aligned;" ::: "memory");
}
__device__ __forceinline__ void tc_ld32(uint32_t* r, uint32_t tmem_addr) {
    asm volatile(
        "tcgen05.ld.sync.aligned.32x32b.x32.b32 "
        "{%0, %1, %2, %3, %4, %5, %6, %7, "
        " %8, %9, %10, %11, %12, %13, %14, %15, "
        " %16, %17, %18, %19, %20, %21, %22, %23, "
        " %24, %25, %26, %27, %28, %29, %30, %31}, [%32];"
        : "=r"(r[0]),  "=r"(r[1]),  "=r"(r[2]),  "=r"(r[3]),
          "=r"(r[4]),  "=r"(r[5]),  "=r"(r[6]),  "=r"(r[7]),
          "=r"(r[8]),  "=r"(r[9]),  "=r"(r[10]), "=r"(r[11]),
          "=r"(r[12]), "=r"(r[13]), "=r"(r[14]), "=r"(r[15]),
          "=r"(r[16]), "=r"(r[17]), "=r"(r[18]), "=r"(r[19]),
          "=r"(r[20]), "=r"(r[21]), "=r"(r[22]), "=r"(r[23]),
          "=r"(r[24]), "=r"(r[25]), "=r"(r[26]), "=r"(r[27]),
          "=r"(r[28]), "=r"(r[29]), "=r"(r[30]), "=r"(r[31])
        : "r"(tmem_addr));
}

// ======================= tile loader (tcgen05 path) =======================
__device__ __forceinline__ void load_chunk(
    uint32_t sbase, int tid, int k0, int K,
    const bf16* a_hi, const bf16* a_lo,
    const bf16* b0_hi, const bf16* b0_lo,
    const bf16* b1_hi, const bf16* b1_lo)
{
#pragma unroll
    for (int t = 0; t < 24; ++t) {
        int c = tid + t * NTHREADS;
        const bf16* src;
        uint32_t doff;
        if (c < 2048) {                       // A tiles (hi then lo)
            int cc = c & 1023;
            int row = cc >> 3, col = cc & 7;
            const bf16* base = (c < 1024) ? a_hi : a_lo;
            src = base + (size_t)row * K + k0 + col * 8;
            doff = ((c < 1024) ? OFF_AHI : OFF_ALO) + swz((uint32_t)row * 128 + col * 16);
        } else {                              // B tiles (hi then lo), 256 rows
            int cc = (c - 2048) & 2047;
            int row = cc >> 3, col = cc & 7;
            bool hi = (c < 4096);
            const bf16* base = (row < 128) ? (hi ? b0_hi : b0_lo)
                                           : (hi ? b1_hi : b1_lo);
            int r = row & 127;
            src = base + (size_t)r * K + k0 + col * 8;
            doff = (hi ? OFF_BHI : OFF_BLO) + swz((uint32_t)row * 128 + col * 16);
        }
        cp16(sbase + doff, src);
    }
}

// ======================= fused GEMM =======================
// MODE 1: gu = x @ Wgu^T slice; cols 0..127 = gate (B=b0), 128..255 = up (B=b1);
//         epilogue = SwiGLU -> write h split (bf16 hi/lo). grid (M/128, I/128).
// MODE 0: out = h @ Wd^T (b0 rows nb*256.., b1 = b0+128 rows); fp32 out. grid (M/128, H/256).
template<int MODE>
__global__ void __launch_bounds__(NTHREADS, 1) __cluster_dims__(1, 1, 1)
mlp_gemm(const bf16* __restrict__ A_hi, const bf16* __restrict__ A_lo,
         const bf16* __restrict__ B_hi, const bf16* __restrict__ B_lo,
         const bf16* __restrict__ B1_hi, const bf16* __restrict__ B1_lo,
         int K, int ldout,
         float* __restrict__ Cout,
         bf16* __restrict__ Hhi, bf16* __restrict__ Hlo)
{
    extern __shared__ __align__(1024) char smem[];
    const int tid = threadIdx.x;
    const int mb = blockIdx.x, nb = blockIdx.y;

    const bf16* a_hi = A_hi + (size_t)mb * BM * K;
    const bf16* a_lo = A_lo + (size_t)mb * BM * K;
    const size_t boff = (MODE == 1) ? (size_t)nb * 128 * K : (size_t)nb * 256 * K;
    const bf16* b0_hi = B_hi + boff;
    const bf16* b0_lo = B_lo + boff;
    const bf16* b1_hi = (MODE == 1) ? (B1_hi + boff) : (B_hi + boff + (size_t)128 * K);
    const bf16* b1_lo = (MODE == 1) ? (B1_lo + boff) : (B_lo + boff + (size_t)128 * K);

#if HAS_TC
    // ---------------- tcgen05 path ----------------
    const uint32_t sb = smem_u32(smem);
    const int wid = tid >> 5;

    if (wid == 0) {
        tc_alloc(sb + 0, 256);
        tc_relinquish();
    }
    if (tid == 0) {
        MBARRIER_INIT(sb + 8, 1);
        MBARRIER_INIT(sb + 16, 1);
    }
    __syncthreads();
    uint32_t tmem;
    asm volatile("ld.shared.b32 %0, [%1];" : "=r"(tmem) : "r"(sb));

    const int nch = K / KC;

    load_chunk(sb + SMEM_STAGE0,               tid, 0,  K, a_hi, a_lo, b0_hi, b0_lo, b1_hi, b1_lo);
    cp_commit();
    load_chunk(sb + SMEM_STAGE0 + STAGE_BYTES, tid, KC, K, a_hi, a_lo, b0_hi, b0_lo, b1_hi, b1_lo);
    cp_commit();

    int ph0 = 0, ph1 = 0;
    for (int i = 0; i < nch; ++i) {
        const int p = i & 1;
        const uint32_t stage = sb + SMEM_STAGE0 + (uint32_t)p * STAGE_BYTES;

        asm volatile("cp.async.wait_group 1;" ::: "memory");
        __syncthreads();

        if (wid == 0 && elect_one()) {
            asm volatile("fence.proxy.async.shared::cta;" ::: "memory");
            const uint64_t adh = make_desc(stage + OFF_AHI);
            const uint64_t adl = make_desc(stage + OFF_ALO);
            const uint64_t bdh = make_desc(stage + OFF_BHI);
            const uint64_t bdl = make_desc(stage + OFF_BLO);
            uint32_t en = (i != 0) ? 1u : 0u;
#pragma unroll
            for (int kk = 0; kk < 4; ++kk) { mma_ss(tmem, adh + kk*2, bdh + kk*2, MMA_IDESC, en); en = 1; }
#pragma unroll
            for (int kk = 0; kk < 4; ++kk) mma_ss(tmem, adh + kk*2, bdl + kk*2, MMA_IDESC, 1);
#pragma unroll
            for (int kk = 0; kk < 4; ++kk) mma_ss(tmem, adl + kk*2, bdh + kk*2, MMA_IDESC, 1);
            tc_commit(sb + 8 + p * 8);
        }

        if (p == 0) { MBARRIER_WAIT_PARITY(sb + 8,  ph0); ph0 ^= 1; }
        else        { MBARRIER_WAIT_PARITY(sb + 16, ph1); ph1 ^= 1; }

        if (i + 2 < nch)
            load_chunk(stage, tid, (i + 2) * KC, K, a_hi, a_lo, b0_hi, b0_lo, b1_hi, b1_lo);
        cp_commit();
    }

    tc_fence_after();

    if (tid < 128) {
        const int m = mb * BM + tid;
        if (MODE == 1) {
            bf16* hh = Hhi + (size_t)m * ldout + (size_t)nb * 128;
            bf16* hl = Hlo + (size_t)m * ldout + (size_t)nb * 128;
#pragma unroll
            for (int c0 = 0; c0 < 128; c0 += 32) {
                uint32_t gr[32], ur[32];
                tc_ld32(gr, tmem + c0);
                tc_ld32(ur, tmem + 128 + c0);
                tc_wait_ld();
#pragma unroll
                for (int j = 0; j < 32; ++j) {
                    float g = __uint_as_float(gr[j]);
                    float u = __uint_as_float(ur[j]);
                    float h = g * u / (1.0f + __expf(-g));
                    bf16 hv = __float2bfloat16(h);
                    float rem = h - __bfloat162float(hv);
                    hh[c0 + j] = hv;
                    hl[c0 + j] = __float2bfloat16(rem);
                }
            }
        } else {
            float* co = Cout + (size_t)m * ldout + (size_t)nb * 256;
#pragma unroll
            for (int c0 = 0; c0 < 256; c0 += 32) {
                uint32_t dr[32];
                tc_ld32(dr, tmem + c0);
                tc_wait_ld();
#pragma unroll
                for (int j = 0; j < 32; ++j) co[c0 + j] = __uint_as_float(dr[j]);
            }
        }
    }
    __syncthreads();
    if (wid == 0) tc_dealloc(tmem, 256);

#else
    // ---------------- SIMT fallback (plain sm_103 target) ----------------
    // 256 threads, 16x16 grid of 8x8 micro-tiles, two 128-col halves at once.
    float* fA  = reinterpret_cast<float*>(smem);          // [8][128]
    float* fB0 = fA  + 8 * 128;                            // [8][128]
    float* fB1 = fB0 + 8 * 128;                            // [8][128]

    const int tx = tid & 15;
    const int ty = tid >> 4;
    const int lr = tid >> 1;            // 0..127
    const int lc = (tid & 1) << 2;      // 0 or 4

    float acc0[8][8], acc1[8][8];
#pragma unroll
    for (int i = 0; i < 8; i++)
#pragma unroll
        for (int j = 0; j < 8; j++) { acc0[i][j] = 0.0f; acc1[i][j] = 0.0f; }

    for (int k0 = 0; k0 < K; k0 += 8) {
        __syncthreads();
#pragma unroll
        for (int c = 0; c < 4; ++c) {
            int k = k0 + lc + c;
            size_t off = (size_t)lr * K + k;
            fA [(lc + c) * 128 + lr] = __bfloat162float(a_hi[off]) + __bfloat162float(a_lo[off]);
            fB0[(lc + c) * 128 + lr] = __bfloat162float(b0_hi[off]) + __bfloat162float(b0_lo[off]);
            fB1[(lc + c) * 128 + lr] = __bfloat162float(b1_hi[off]) + __bfloat162float(b1_lo[off]);
        }
        __syncthreads();
#pragma unroll
        for (int k = 0; k < 8; k++) {
            float ra[8], rb0[8], rb1[8];
#pragma unroll
            for (int i = 0; i < 8; i++) ra[i]  = fA [k * 128 + ty * 8 + i];
#pragma unroll
            for (int j = 0; j < 8; j++) { rb0[j] = fB0[k * 128 + tx * 8 + j]; rb1[j] = fB1[k * 128 + tx * 8 + j]; }
#pragma unroll
            for (int i = 0; i < 8; i++)
#pragma unroll
                for (int j = 0; j < 8; j++) {
                    acc0[i][j] = fmaf(ra[i], rb0[j], acc0[i][j]);
                    acc1[i][j] = fmaf(ra[i], rb1[j], acc1[i][j]);
                }
        }
    }

    if (MODE == 1) {
#pragma unroll
        for (int i = 0; i < 8; i++) {
            int m = mb * BM + ty * 8 + i;
            bf16* hh = Hhi + (size_t)m * ldout + (size_t)nb * 128 + tx * 8;
            bf16* hl = Hlo + (size_t)m * ldout + (size_t)nb * 128 + tx * 8;
#pragma unroll
            for (int j = 0; j < 8; j++) {
                float g = acc0[i][j], u = acc1[i][j];
                float h = g * u / (1.0f + __expf(-g));
                bf16 hv = __float2bfloat16(h);
                hh[j] = hv;
                hl[j] = __float2bfloat16(h - __bfloat162float(hv));
            }
        }
    } else {
#pragma unroll
        for (int i = 0; i < 8; i++) {
            int m = mb * BM + ty * 8 + i;
            float* co = Cout + (size_t)m * ldout + (size_t)nb * 256 + tx * 8;
#pragma unroll
            for (int j = 0; j < 8; j++) { co[j] = acc0[i][j]; co[128 + j] = acc1[i][j]; }
        }
    }
#endif
}

// ======================= fp32 -> bf16 hi/lo split =======================
__global__ void split_kernel(const float4* __restrict__ src,
                             __nv_bfloat162* __restrict__ hi,
                             __nv_bfloat162* __restrict__ lo, long n4)
{
    long i = (long)blockIdx.x * blockDim.x + threadIdx.x;
    if (i >= n4) return;
    float4 v = src[i];
    bf16 h0 = __float2bfloat16(v.x);
    bf16 h1 = __float2bfloat16(v.y);
    bf16 h2 = __float2bfloat16(v.z);
    bf16 h3 = __float2bfloat16(v.w);
    bf16 l0 = __float2bfloat16(v.x - __bfloat162float(h0));
    bf16 l1 = __float2bfloat16(v.y - __bfloat162float(h1));
    bf16 l2 = __float2bfloat16(v.z - __bfloat162float(h2));
    bf16 l3 = __float2bfloat16(v.w - __bfloat162float(h3));
    hi[2*i]   = __halves2bfloat162(h0, h1);
    hi[2*i+1] = __halves2bfloat162(h2, h3);
    lo[2*i]   = __halves2bfloat162(l0, l1);
    lo[2*i+1] = __halves2bfloat162(l2, l3);
}

// ======================= launch =======================
extern "C" void kernel_launch(void* const* d_in, const int* in_sizes, int n_in,
                              void* d_out, int out_size)
{
    const float* x   = (const float*)d_in[0];
    const float* wgu = (const float*)d_in[1];
    const float* wd  = (const float*)d_in[2];
    float* out       = (float*)d_out;

    bf16 *x_hi, *x_lo, *wgu_hi, *wgu_lo, *wd_hi, *wd_lo, *h_hi, *h_lo;
    cudaGetSymbolAddress((void**)&x_hi,  g_x_hi);
    cudaGetSymbolAddress((void**)&x_lo,  g_x_lo);
    cudaGetSymbolAddress((void**)&wgu_hi, g_wgu_hi);
    cudaGetSymbolAddress((void**)&wgu_lo, g_wgu_lo);
    cudaGetSymbolAddress((void**)&wd_hi, g_wd_hi);
    cudaGetSymbolAddress((void**)&wd_lo, g_wd_lo);
    cudaGetSymbolAddress((void**)&h_hi,  g_h_hi);
    cudaGetSymbolAddress((void**)&h_lo,  g_h_lo);

    cudaFuncSetAttribute(mlp_gemm<0>, cudaFuncAttributeMaxDynamicSharedMemorySize, SMEM_TOTAL);
    cudaFuncSetAttribute(mlp_gemm<1>, cudaFuncAttributeMaxDynamicSharedMemorySize, SMEM_TOTAL);

    // split inputs into bf16 hi/lo
    {
        long n4 = (long)M_DIM * H_DIM / 4;
        split_kernel<<<(unsigned)((n4 + 255) / 256), 256>>>(
            (const float4*)x, (__nv_bfloat162*)x_hi, (__nv_bfloat162*)x_lo, n4);
    }
    {
        long n4 = (long)2 * I_DIM * H_DIM / 4;
        split_kernel<<<(unsigned)((n4 + 255) / 256), 256>>>(
            (const float4*)wgu, (__nv_bfloat162*)wgu_hi, (__nv_bfloat162*)wgu_lo, n4);
    }
    {
        long n4 = (long)H_DIM * I_DIM / 4;
        split_kernel<<<(unsigned)((n4 + 255) / 256), 256>>>(
            (const float4*)wd, (__nv_bfloat162*)wd_hi, (__nv_bfloat162*)wd_lo, n4);
    }

    // GEMM1 (fused SwiGLU + h split): grid (M/128, I/128)
    mlp_gemm<1><<<dim3(M_DIM / BM, I_DIM / 128), NTHREADS, SMEM_TOTAL>>>(
        x_hi, x_lo,
        wgu_hi, wgu_lo,
        wgu_hi + (size_t)I_DIM * H_DIM, wgu_lo + (size_t)I_DIM * H_DIM,
        H_DIM, I_DIM,
        nullptr, h_hi, h_lo);

    // GEMM2: out = h @ Wd^T: grid (M/128, H/256)
    mlp_gemm<0><<<dim3(M_DIM / BM, H_DIM / BN), NTHREADS, SMEM_TOTAL>>>(
        h_hi, h_lo,
        wd_hi, wd_lo,
        nullptr, nullptr,
        I_DIM, H_DIM,
        out, nullptr, nullptr);
}

// round 5
// speedup vs baseline: 11.2997x; 1.5610x over previous
#include <cuda_runtime.h>
#include <cuda_bf16.h>
#include <cstdint>
#include <math.h>

typedef __nv_bfloat16 bf16;

// ---- arch gate: tcgen05 only exists on arch-specific (sm_103a) targets ----
#if defined(__CUDA_ARCH__) && ( \
      defined(__CUDA_ARCH_FEAT_SM103_ALL) || \
      defined(__CUDA_ARCH_FEAT_SM100_ALL) || \
      (defined(__CUDA_ARCH_SPECIFIC__) && (__CUDA_ARCH_SPECIFIC__ == 1030 || __CUDA_ARCH_SPECIFIC__ == 1000)) )
#define HAS_TC 1
#else
#define HAS_TC 0
#endif

// ---- problem dims ----
#define M_DIM 4096
#define H_DIM 4096
#define I_DIM 11008

// ---- GEMM tile config (tcgen05 path) ----
#define BM 128
#define BN 256
#define KC 64           // bf16 elems per K-chunk -> 128B rows (SW128 atom width)
#define NTHREADS 256

// ---- smem stage layout (bytes) ----
#define OFF_AHI 0
#define OFF_ALO (16*1024)
#define OFF_BHI (32*1024)
#define OFF_BLO (64*1024)
#define STAGE_BYTES (96*1024)
#define SMEM_STAGE0 1024
#define SMEM_TOTAL (SMEM_STAGE0 + 2*STAGE_BYTES)   // 197632 B

// mbarrier offsets (within smem control area)
#define MB_MMA0 8
#define MB_MMA1 16
#define MB_LD0  24
#define MB_LD1  32

// idesc: kind::f16, dtype=F32(1<<4), atype=BF16(1<<7), btype=BF16(1<<10),
// N=256 -> (256/8)<<17, M=128 -> (128/16)<<24
#define MMA_IDESC ((1u<<4)|(1u<<7)|(1u<<10)|((BN/8)<<17)|((BM/16)<<24))

// SW128 K-major smem descriptor base (layout=2, version=1, SBO=64, LBO=1)
#define SMEM_DESC_BASE_SW128 \
    ((uint64_t(2) << 61) | (uint64_t(1) << 46) | (uint64_t(64) << 32) | (uint64_t(1) << 16))

// ---- device scratch (allocation-free rule) ----
__device__ bf16 g_x_hi [(size_t)M_DIM * H_DIM];
__device__ bf16 g_x_lo [(size_t)M_DIM * H_DIM];
__device__ bf16 g_wgu_hi[(size_t)2 * I_DIM * H_DIM];
__device__ bf16 g_wgu_lo[(size_t)2 * I_DIM * H_DIM];
__device__ bf16 g_wd_hi [(size_t)H_DIM * I_DIM];
__device__ bf16 g_wd_lo [(size_t)H_DIM * I_DIM];
__device__ bf16 g_h_hi  [(size_t)M_DIM * I_DIM];
__device__ bf16 g_h_lo  [(size_t)M_DIM * I_DIM];

// ======================= generic PTX helpers =======================

__device__ __forceinline__ uint32_t smem_u32(const void* p) {
    uint32_t a;
    asm("{ .reg .u64 t; cvta.to.shared.u64 t, %1; cvt.u32.u64 %0, t; }" : "=r"(a) : "l"(p));
    return a;
}

__device__ __forceinline__ uint32_t elect_one() {
    uint32_t pred;
    asm volatile("{\n\t.reg .pred p;\n\telect.sync _|p, 0xFFFFFFFF;\n\tselp.b32 %0, 1, 0, p;\n\t}" : "=r"(pred));
    return pred;
}

__device__ __forceinline__ uint32_t swz(uint32_t off) { return off ^ ((off >> 3) & 0x70); }

__device__ __forceinline__ void cp16(uint32_t dst, const void* src) {
    asm volatile("cp.async.cg.shared.global [%0], [%1], 16;" :: "r"(dst), "l"(src) : "memory");
}

// Arrive on mbarrier when all of this thread's prior cp.asyncs complete.
// .noinc is REQUIRED: the default form pre-increments the pending count
// (self-cancelling), so a barrier initialized with count=128 would never flip.
__device__ __forceinline__ void cp_arrive(uint32_t mbar) {
    asm volatile("cp.async.mbarrier.arrive.noinc.shared::cta.b64 [%0];" :: "r"(mbar) : "memory");
}

__device__ __forceinline__ uint64_t make_desc(uint32_t addr) {
    return SMEM_DESC_BASE_SW128 | ((uint64_t)(addr >> 4) & 0x3FFF);
}

#define MBARRIER_INIT(mbar, count) \
    asm volatile("mbarrier.init.shared.b64 [%0], %1;" \
        :: "r"((uint32_t)(mbar)), "r"((uint32_t)(count)) : "memory")

#define MBARRIER_WAIT_PARITY(mbar_addr, phase_parity) do { \
    uint32_t _mbar = (uint32_t)(mbar_addr); \
    uint32_t _parity = (uint32_t)(phase_parity); \
    uint32_t _done; \
    asm volatile( \
        "{\n\t.reg .pred p;\n\t" \
        "mbarrier.try_wait.parity.acquire.cta.shared::cta.b64 p, [%1], %2;\n\t" \
        "selp.b32 %0, 1, 0, p;\n\t}" \
        : "=r"(_done) : "r"(_mbar), "r"(_parity) : "memory"); \
    if (!_done) { \
        asm volatile( \
            "{\n\t.reg .pred P1;\n\t" \
            "WAIT_LOOP_%=:\n\t" \
            "mbarrier.try_wait.parity.acquire.cta.shared::cta.b64 P1, [%0], %1, 0x989680;\n\t" \
            "@P1 bra.uni WAIT_DONE_%=;\n\t" \
            "bra.uni WAIT_LOOP_%=;\n\t" \
            "WAIT_DONE_%=:\n\t}" \
            :: "r"(_mbar), "r"(_parity) : "memory"); \
    } \
} while (0)

// ======================= tcgen05 helpers =======================

__device__ __forceinline__ void mma_ss(uint32_t d, uint64_t ad, uint64_t bd,
                                       uint32_t idesc, uint32_t en) {
    asm volatile(
        "{\n\t"
        ".reg .pred p;\n\t"
        "setp.ne.u32 p, %4, 0;\n\t"
        "tcgen05.mma.cta_group::1.kind::f16 [%0], %1, %2, %3, {%5, %5, %5, %5}, p;\n\t"
        "}"
        :: "r"(d), "l"(ad), "l"(bd), "r"(idesc), "r"(en), "r"(0u)
        : "memory");
}

__device__ __forceinline__ void tc_alloc(uint32_t smem_result_addr, uint32_t nCols) {
    asm volatile("tcgen05.alloc.cta_group::1.sync.aligned.shared::cta.b32 [%0], %1;"
        :: "r"(smem_result_addr), "r"(nCols) : "memory");
}
__device__ __forceinline__ void tc_dealloc(uint32_t tmem_addr, uint32_t nCols) {
    asm volatile("tcgen05.dealloc.cta_group::1.sync.aligned.b32 %0, %1;"
        :: "r"(tmem_addr), "r"(nCols));
}
__device__ __forceinline__ void tc_relinquish() {
    asm volatile("tcgen05.relinquish_alloc_permit.cta_group::1.sync.aligned;");
}
__device__ __forceinline__ void tc_commit(uint32_t mbar) {
    asm volatile("tcgen05.commit.cta_group::1.mbarrier::arrive::one.shared::cluster.b64 [%0];"
        :: "r"(mbar) : "memory");
}
__device__ __forceinline__ void tc_fence_after() {
    asm volatile("tcgen05.fence::after_thread_sync;" ::: "memory");
}
__device__ __forceinline__ void tc_wait_ld() {
    asm volatile("tcgen05.wait::ld.sync.aligned;" ::: "memory");
}
__device__ __forceinline__ void tc_ld32(uint32_t* r, uint32_t tmem_addr) {
    asm volatile(
        "tcgen05.ld.sync.aligned.32x32b.x32.b32 "
        "{%0, %1, %2, %3, %4, %5, %6, %7, "
        " %8, %9, %10, %11, %12, %13, %14, %15, "
        " %16, %17, %18, %19, %20, %21, %22, %23, "
        " %24, %25, %26, %27, %28, %29, %30, %31}, [%32];"
        : "=r"(r[0]),  "=r"(r[1]),  "=r"(r[2]),  "=r"(r[3]),
          "=r"(r[4]),  "=r"(r[5]),  "=r"(r[6]),  "=r"(r[7]),
          "=r"(r[8]),  "=r"(r[9]),  "=r"(r[10]), "=r"(r[11]),
          "=r"(r[12]), "=r"(r[13]), "=r"(r[14]), "=r"(r[15]),
          "=r"(r[16]), "=r"(r[17]), "=r"(r[18]), "=r"(r[19]),
          "=r"(r[20]), "=r"(r[21]), "=r"(r[22]), "=r"(r[23]),
          "=r"(r[24]), "=r"(r[25]), "=r"(r[26]), "=r"(r[27]),
          "=r"(r[28]), "=r"(r[29]), "=r"(r[30]), "=r"(r[31])
        : "r"(tmem_addr));
}

// ======================= tile loader (128 loader threads) =======================
// Stage: Ahi/Alo [128 x 64 bf16], Bhi/Blo [256 x 64 bf16], SW128 K-major.
// 6144 x 16B units / 128 threads = 48 each.
__device__ __forceinline__ void load_chunk128(
    uint32_t sbase, int t, int k0, int K,
    const bf16* a_hi, const bf16* a_lo,
    const bf16* b0_hi, const bf16* b0_lo,
    const bf16* b1_hi, const bf16* b1_lo)
{
#pragma unroll
    for (int j = 0; j < 48; ++j) {
        int c = t + j * 128;
        const bf16* src;
        uint32_t doff;
        if (c < 2048) {                       // A tiles (hi then lo)
            int cc = c & 1023;
            int row = cc >> 3, col = cc & 7;
            const bf16* base = (c < 1024) ? a_hi : a_lo;
            src = base + (size_t)row * K + k0 + col * 8;
            doff = ((c < 1024) ? OFF_AHI : OFF_ALO) + swz((uint32_t)row * 128 + col * 16);
        } else {                              // B tiles (hi then lo), 256 rows
            int cc = (c - 2048) & 2047;
            int row = cc >> 3, col = cc & 7;
            bool hi = (c < 4096);
            const bf16* base = (row < 128) ? (hi ? b0_hi : b0_lo)
                                           : (hi ? b1_hi : b1_lo);
            int r = row & 127;
            src = base + (size_t)r * K + k0 + col * 8;
            doff = (hi ? OFF_BHI : OFF_BLO) + swz((uint32_t)row * 128 + col * 16);
        }
        cp16(sbase + doff, src);
    }
}

// ======================= fused GEMM =======================
// MODE 1: gu = x @ Wgu^T slice; cols 0..127 = gate (b0), 128..255 = up (b1);
//         epilogue = SwiGLU -> h split (bf16 hi/lo). grid (M/128, I/128).
// MODE 0: out = h @ Wd^T; fp32 out. grid (M/128, H/256).
template<int MODE>
__global__ void __launch_bounds__(NTHREADS, 1) __cluster_dims__(1, 1, 1)
mlp_gemm(const bf16* __restrict__ A_hi, const bf16* __restrict__ A_lo,
         const bf16* __restrict__ B_hi, const bf16* __restrict__ B_lo,
         const bf16* __restrict__ B1_hi, const bf16* __restrict__ B1_lo,
         int K, int ldout,
         float* __restrict__ Cout,
         bf16* __restrict__ Hhi, bf16* __restrict__ Hlo)
{
    extern __shared__ __align__(1024) char smem[];
    const int tid = threadIdx.x;
    const int mb = blockIdx.x, nb = blockIdx.y;

    const bf16* a_hi = A_hi + (size_t)mb * BM * K;
    const bf16* a_lo = A_lo + (size_t)mb * BM * K;
    const size_t boff = (MODE == 1) ? (size_t)nb * 128 * K : (size_t)nb * 256 * K;
    const bf16* b0_hi = B_hi + boff;
    const bf16* b0_lo = B_lo + boff;
    const bf16* b1_hi = (MODE == 1) ? (B1_hi + boff) : (B_hi + boff + (size_t)128 * K);
    const bf16* b1_lo = (MODE == 1) ? (B1_lo + boff) : (B_lo + boff + (size_t)128 * K);

#if HAS_TC
    // ---------------- tcgen05 warp-specialized path ----------------
    const uint32_t sb = smem_u32(smem);
    const int wid = tid >> 5;

    if (wid == 0) {
        tc_alloc(sb + 0, 256);
        tc_relinquish();
    }
    if (tid == 0) {
        MBARRIER_INIT(sb + MB_MMA0, 1);
        MBARRIER_INIT(sb + MB_MMA1, 1);
        MBARRIER_INIT(sb + MB_LD0, 128);
        MBARRIER_INIT(sb + MB_LD1, 128);
    }
    __syncthreads();
    uint32_t tmem;
    asm volatile("ld.shared.b32 %0, [%1];" : "=r"(tmem) : "r"(sb));

    const int nch = K / KC;          // even for both GEMMs (64, 172)

    if (wid >= 4) {
        // ---- loader warps: 128 threads ----
        const int t = tid - 128;
        load_chunk128(sb + SMEM_STAGE0, t, 0, K, a_hi, a_lo, b0_hi, b0_lo, b1_hi, b1_lo);
        cp_arrive(sb + MB_LD0);
        load_chunk128(sb + SMEM_STAGE0 + STAGE_BYTES, t, KC, K, a_hi, a_lo, b0_hi, b0_lo, b1_hi, b1_lo);
        cp_arrive(sb + MB_LD1);

        int phm0 = 0, phm1 = 0;
        for (int i = 2; i < nch; ++i) {
            const int p = i & 1;
            // wait until MMAs consuming buffer p (chunk i-2) are done
            if (p == 0) { MBARRIER_WAIT_PARITY(sb + MB_MMA0, phm0); phm0 ^= 1; }
            else        { MBARRIER_WAIT_PARITY(sb + MB_MMA1, phm1); phm1 ^= 1; }
            load_chunk128(sb + SMEM_STAGE0 + (uint32_t)p * STAGE_BYTES, t, i * KC, K,
                          a_hi, a_lo, b0_hi, b0_lo, b1_hi, b1_lo);
            cp_arrive(sb + MB_LD0 + p * 8);
        }
    } else if (wid == 0) {
        // ---- MMA issue warp: never waits for MMA completion ----
        int phl0 = 0, phl1 = 0;
        for (int i = 0; i < nch; ++i) {
            const int p = i & 1;
            if (p == 0) { MBARRIER_WAIT_PARITY(sb + MB_LD0, phl0); phl0 ^= 1; }
            else        { MBARRIER_WAIT_PARITY(sb + MB_LD1, phl1); phl1 ^= 1; }
            if (elect_one()) {
                asm volatile("fence.proxy.async.shared::cta;" ::: "memory");
                const uint32_t stage = sb + SMEM_STAGE0 + (uint32_t)p * STAGE_BYTES;
                const uint64_t adh = make_desc(stage + OFF_AHI);
                const uint64_t adl = make_desc(stage + OFF_ALO);
                const uint64_t bdh = make_desc(stage + OFF_BHI);
                const uint64_t bdl = make_desc(stage + OFF_BLO);
                uint32_t en = (i != 0) ? 1u : 0u;
#pragma unroll
                for (int kk = 0; kk < 4; ++kk) { mma_ss(tmem, adh + kk*2, bdh + kk*2, MMA_IDESC, en); en = 1; }
#pragma unroll
                for (int kk = 0; kk < 4; ++kk) mma_ss(tmem, adh + kk*2, bdl + kk*2, MMA_IDESC, 1);
#pragma unroll
                for (int kk = 0; kk < 4; ++kk) mma_ss(tmem, adl + kk*2, bdh + kk*2, MMA_IDESC, 1);
                tc_commit(sb + MB_MMA0 + p * 8);
            }
        }
        // final commits: each buffer committed nch/2 times; loaders consumed
        // parities 0..nch/2-2 -> remaining phase parity = (nch/2-1)&1
        const int fpar = ((nch / 2) - 1) & 1;
        MBARRIER_WAIT_PARITY(sb + MB_MMA0, fpar);
        MBARRIER_WAIT_PARITY(sb + MB_MMA1, fpar);
    }
    // warps 1-3 fall through; warp 0 holds everyone until all MMAs are done
    __syncthreads();
    tc_fence_after();

    // ---- epilogue: stage in smem for coalesced global writes ----
    if (MODE == 1) {
        bf16* sH = reinterpret_cast<bf16*>(smem);                 // [128][130] (pad 2)
        bf16* sL = sH + 128 * 130;
        if (tid < 128) {
#pragma unroll
            for (int c0 = 0; c0 < 128; c0 += 32) {
                uint32_t gr[32], ur[32];
                tc_ld32(gr, tmem + c0);
                tc_ld32(ur, tmem + 128 + c0);
                tc_wait_ld();
#pragma unroll
                for (int j = 0; j < 32; ++j) {
                    float g = __uint_as_float(gr[j]);
                    float u = __uint_as_float(ur[j]);
                    float h = g * u / (1.0f + __expf(-g));
                    bf16 hv = __float2bfloat16(h);
                    sH[tid * 130 + c0 + j] = hv;
                    sL[tid * 130 + c0 + j] = __float2bfloat16(h - __bfloat162float(hv));
                }
            }
        }
        __syncthreads();
        // coalesced copy out: 128 rows x 64 bf162 per tile
        const size_t obase = (size_t)(mb * BM) * ldout + (size_t)nb * 128;
#pragma unroll 4
        for (int u = tid; u < 128 * 64; u += NTHREADS) {
            int r = u >> 6, cu = u & 63;
            __nv_bfloat162 vh = *reinterpret_cast<__nv_bfloat162*>(&sH[r * 130 + cu * 2]);
            __nv_bfloat162 vl = *reinterpret_cast<__nv_bfloat162*>(&sL[r * 130 + cu * 2]);
            *reinterpret_cast<__nv_bfloat162*>(Hhi + obase + (size_t)r * ldout + cu * 2) = vh;
            *reinterpret_cast<__nv_bfloat162*>(Hlo + obase + (size_t)r * ldout + cu * 2) = vl;
        }
    } else {
        float* sC = reinterpret_cast<float*>(smem);               // [128][257] (pad 1)
        if (tid < 128) {
#pragma unroll
            for (int c0 = 0; c0 < 256; c0 += 32) {
                uint32_t dr[32];
                tc_ld32(dr, tmem + c0);
                tc_wait_ld();
#pragma unroll
                for (int j = 0; j < 32; ++j)
                    sC[tid * 257 + c0 + j] = __uint_as_float(dr[j]);
            }
        }
        __syncthreads();
        const size_t obase = (size_t)(mb * BM) * ldout + (size_t)nb * 256;
#pragma unroll 4
        for (int u = tid; u < 128 * 256; u += NTHREADS) {
            int r = u >> 8, col = u & 255;
            Cout[obase + (size_t)r * ldout + col] = sC[r * 257 + col];
        }
    }
    __syncthreads();
    if (wid == 0) tc_dealloc(tmem, 256);

#else
    // ---------------- SIMT fallback (plain sm_103 target) ----------------
    float* fA  = reinterpret_cast<float*>(smem);          // [8][128]
    float* fB0 = fA  + 8 * 128;                            // [8][128]
    float* fB1 = fB0 + 8 * 128;                            // [8][128]

    const int tx = tid & 15;
    const int ty = tid >> 4;
    const int lr = tid >> 1;
    const int lc = (tid & 1) << 2;

    float acc0[8][8], acc1[8][8];
#pragma unroll
    for (int i = 0; i < 8; i++)
#pragma unroll
        for (int j = 0; j < 8; j++) { acc0[i][j] = 0.0f; acc1[i][j] = 0.0f; }

    for (int k0 = 0; k0 < K; k0 += 8) {
        __syncthreads();
#pragma unroll
        for (int c = 0; c < 4; ++c) {
            int k = k0 + lc + c;
            size_t off = (size_t)lr * K + k;
            fA [(lc + c) * 128 + lr] = __bfloat162float(a_hi[off]) + __bfloat162float(a_lo[off]);
            fB0[(lc + c) * 128 + lr] = __bfloat162float(b0_hi[off]) + __bfloat162float(b0_lo[off]);
            fB1[(lc + c) * 128 + lr] = __bfloat162float(b1_hi[off]) + __bfloat162float(b1_lo[off]);
        }
        __syncthreads();
#pragma unroll
        for (int k = 0; k < 8; k++) {
            float ra[8], rb0[8], rb1[8];
#pragma unroll
            for (int i = 0; i < 8; i++) ra[i]  = fA [k * 128 + ty * 8 + i];
#pragma unroll
            for (int j = 0; j < 8; j++) { rb0[j] = fB0[k * 128 + tx * 8 + j]; rb1[j] = fB1[k * 128 + tx * 8 + j]; }
#pragma unroll
            for (int i = 0; i < 8; i++)
#pragma unroll
                for (int j = 0; j < 8; j++) {
                    acc0[i][j] = fmaf(ra[i], rb0[j], acc0[i][j]);
                    acc1[i][j] = fmaf(ra[i], rb1[j], acc1[i][j]);
                }
        }
    }

    if (MODE == 1) {
#pragma unroll
        for (int i = 0; i < 8; i++) {
            int m = mb * BM + ty * 8 + i;
            bf16* hh = Hhi + (size_t)m * ldout + (size_t)nb * 128 + tx * 8;
            bf16* hl = Hlo + (size_t)m * ldout + (size_t)nb * 128 + tx * 8;
#pragma unroll
            for (int j = 0; j < 8; j++) {
                float g = acc0[i][j], u = acc1[i][j];
                float h = g * u / (1.0f + __expf(-g));
                bf16 hv = __float2bfloat16(h);
                hh[j] = hv;
                hl[j] = __float2bfloat16(h - __bfloat162float(hv));
            }
        }
    } else {
#pragma unroll
        for (int i = 0; i < 8; i++) {
            int m = mb * BM + ty * 8 + i;
            float* co = Cout + (size_t)m * ldout + (size_t)nb * 256 + tx * 8;
#pragma unroll
            for (int j = 0; j < 8; j++) { co[j] = acc0[i][j]; co[128 + j] = acc1[i][j]; }
        }
    }
#endif
}

// ======================= fp32 -> bf16 hi/lo split =======================
__global__ void split_kernel(const float4* __restrict__ src,
                             __nv_bfloat162* __restrict__ hi,
                             __nv_bfloat162* __restrict__ lo, long n4)
{
    long i = (long)blockIdx.x * blockDim.x + threadIdx.x;
    if (i >= n4) return;
    float4 v = src[i];
    bf16 h0 = __float2bfloat16(v.x);
    bf16 h1 = __float2bfloat16(v.y);
    bf16 h2 = __float2bfloat16(v.z);
    bf16 h3 = __float2bfloat16(v.w);
    bf16 l0 = __float2bfloat16(v.x - __bfloat162float(h0));
    bf16 l1 = __float2bfloat16(v.y - __bfloat162float(h1));
    bf16 l2 = __float2bfloat16(v.z - __bfloat162float(h2));
    bf16 l3 = __float2bfloat16(v.w - __bfloat162float(h3));
    hi[2*i]   = __halves2bfloat162(h0, h1);
    hi[2*i+1] = __halves2bfloat162(h2, h3);
    lo[2*i]   = __halves2bfloat162(l0, l1);
    lo[2*i+1] = __halves2bfloat162(l2, l3);
}

// ======================= launch =======================
extern "C" void kernel_launch(void* const* d_in, const int* in_sizes, int n_in,
                              void* d_out, int out_size)
{
    const float* x   = (const float*)d_in[0];
    const float* wgu = (const float*)d_in[1];
    const float* wd  = (const float*)d_in[2];
    float* out       = (float*)d_out;

    bf16 *x_hi, *x_lo, *wgu_hi, *wgu_lo, *wd_hi, *wd_lo, *h_hi, *h_lo;
    cudaGetSymbolAddress((void**)&x_hi,  g_x_hi);
    cudaGetSymbolAddress((void**)&x_lo,  g_x_lo);
    cudaGetSymbolAddress((void**)&wgu_hi, g_wgu_hi);
    cudaGetSymbolAddress((void**)&wgu_lo, g_wgu_lo);
    cudaGetSymbolAddress((void**)&wd_hi, g_wd_hi);
    cudaGetSymbolAddress((void**)&wd_lo, g_wd_lo);
    cudaGetSymbolAddress((void**)&h_hi,  g_h_hi);
    cudaGetSymbolAddress((void**)&h_lo,  g_h_lo);

    cudaFuncSetAttribute(mlp_gemm<0>, cudaFuncAttributeMaxDynamicSharedMemorySize, SMEM_TOTAL);
    cudaFuncSetAttribute(mlp_gemm<1>, cudaFuncAttributeMaxDynamicSharedMemorySize, SMEM_TOTAL);

    // split inputs into bf16 hi/lo
    {
        long n4 = (long)M_DIM * H_DIM / 4;
        split_kernel<<<(unsigned)((n4 + 255) / 256), 256>>>(
            (const float4*)x, (__nv_bfloat162*)x_hi, (__nv_bfloat162*)x_lo, n4);
    }
    {
        long n4 = (long)2 * I_DIM * H_DIM / 4;
        split_kernel<<<(unsigned)((n4 + 255) / 256), 256>>>(
            (const float4*)wgu, (__nv_bfloat162*)wgu_hi, (__nv_bfloat162*)wgu_lo, n4);
    }
    {
        long n4 = (long)H_DIM * I_DIM / 4;
        split_kernel<<<(unsigned)((n4 + 255) / 256), 256>>>(
            (const float4*)wd, (__nv_bfloat162*)wd_hi, (__nv_bfloat162*)wd_lo, n4);
    }

    // GEMM1 (fused SwiGLU + h split): grid (M/128, I/128)
    mlp_gemm<1><<<dim3(M_DIM / BM, I_DIM / 128), NTHREADS, SMEM_TOTAL>>>(
        x_hi, x_lo,
        wgu_hi, wgu_lo,
        wgu_hi + (size_t)I_DIM * H_DIM, wgu_lo + (size_t)I_DIM * H_DIM,
        H_DIM, I_DIM,
        nullptr, h_hi, h_lo);

    // GEMM2: out = h @ Wd^T: grid (M/128, H/256)
    mlp_gemm<0><<<dim3(M_DIM / BM, H_DIM / BN), NTHREADS, SMEM_TOTAL>>>(
        h_hi, h_lo,
        wd_hi, wd_lo,
        nullptr, nullptr,
        I_DIM, H_DIM,
        out, nullptr, nullptr);
}